// round 9
// baseline (speedup 1.0000x reference)
#include <cuda_runtime.h>
#include <math.h>
#include <stdint.h>

#define B_    2048
#define S_    100
#define POS_  2
#define E_    256
#define H_    256
#define G4_   1024
#define BS_   (B_*S_)

__device__ float g_emb[(size_t)S_*B_*E_];
__device__ float g_encgx[(size_t)S_*B_*G4_];
__device__ float g_encout[(size_t)S_*B_*H_];
__device__ float g_kptr[(size_t)S_*B_*H_];
__device__ float g_kgl[(size_t)S_*B_*H_];
__device__ float g_h[B_*H_];
__device__ float g_c[B_*H_];
__device__ float g_gx[B_*G4_];
__device__ float g_gh[B_*G4_];
__device__ float g_q[B_*H_];
__device__ float g_query[B_*H_];
__device__ unsigned char g_mask[B_*S_];
__device__ float g_decin[B_*E_];
__device__ unsigned g_keys[2*S_];
__device__ unsigned g_cnt = 0;
__device__ unsigned g_gen = 0;

__device__ __forceinline__ void gsync() {
    __syncthreads();
    if (threadIdx.x == 0) {
        __threadfence();
        unsigned gen = *(volatile unsigned*)&g_gen;
        if (atomicAdd(&g_cnt, 1u) == gridDim.x - 1) {
            g_cnt = 0;
            __threadfence();
            *(volatile unsigned*)&g_gen = gen + 1u;
        } else {
            while (*(volatile unsigned*)&g_gen == gen) { __nanosleep(64); }
            __threadfence();
        }
    }
    __syncthreads();
}

__device__ __forceinline__ float xla_tanh(float x) {
    const float CL = 7.90531110763549805f;
    float xc = fminf(fmaxf(x, -CL), CL);
    float x2 = __fmul_rn(xc, xc);
    float p = -2.76076847742355e-16f;
    p = __fadd_rn(__fmul_rn(x2, p),  2.00018790482477e-13f);
    p = __fadd_rn(__fmul_rn(x2, p), -8.60467152213735e-11f);
    p = __fadd_rn(__fmul_rn(x2, p),  5.12229709037114e-08f);
    p = __fadd_rn(__fmul_rn(x2, p),  1.48572235717979e-05f);
    p = __fadd_rn(__fmul_rn(x2, p),  6.37261928875436e-04f);
    p = __fadd_rn(__fmul_rn(x2, p),  4.89352455891786e-03f);
    float num = __fmul_rn(xc, p);
    float q = 1.19825839466702e-06f;
    q = __fadd_rn(__fmul_rn(x2, q),  1.18534705686654e-04f);
    q = __fadd_rn(__fmul_rn(x2, q),  2.26843463243900e-03f);
    q = __fadd_rn(__fmul_rn(x2, q),  4.89352518554385e-03f);
    float r = __fdiv_rn(num, q);
    return fabsf(x) < 0.0004f ? x : r;
}
__device__ __forceinline__ float xla_sigmoid(float x) {
    return __fdiv_rn(1.0f, __fadd_rn(1.0f, expf(-x)));
}

__device__ __forceinline__ unsigned rotl32(unsigned x, int d) {
    return (x << d) | (x >> (32 - d));
}
__device__ __forceinline__ void threefry(unsigned ks0, unsigned ks1,
                                         unsigned &x0, unsigned &x1) {
    unsigned ks2 = ks0 ^ ks1 ^ 0x1BD11BDAu;
    x0 += ks0; x1 += ks1;
#define TF_R(r) { x0 += x1; x1 = rotl32(x1, r); x1 ^= x0; }
    TF_R(13) TF_R(15) TF_R(26) TF_R(6)  x0 += ks1; x1 += ks2 + 1u;
    TF_R(17) TF_R(29) TF_R(16) TF_R(24) x0 += ks2; x1 += ks0 + 2u;
    TF_R(13) TF_R(15) TF_R(26) TF_R(6)  x0 += ks0; x1 += ks1 + 3u;
    TF_R(17) TF_R(29) TF_R(16) TF_R(24) x0 += ks1; x1 += ks2 + 4u;
    TF_R(13) TF_R(15) TF_R(26) TF_R(6)  x0 += ks2; x1 += ks0 + 5u;
#undef TF_R
}

// Partitionable random_bits (jax >= 0.4.30 default):
// bits[i] = out0 ^ out1 of threefry2x32(key, (hi(i)=0, lo(i)=i))
__device__ __forceinline__ float gumbel_at(unsigned k0, unsigned k1, unsigned i) {
    unsigned x0 = 0u, x1 = i;
    threefry(k0, k1, x0, x1);
    unsigned bits = x0 ^ x1;
    float f = __fadd_rn(__uint_as_float((bits >> 9) | 0x3f800000u), -1.0f);
    const float TINY = 1.17549435e-38f;
    float u = fmaxf(TINY, __fadd_rn(__fmul_rn(f, 1.0f - TINY), TINY));
    return -logf(-logf(u));
}

struct AttnSh {
    float sq[H_];
    float sv[H_];
    float su[112];
    float ws[112];
    float red[4];
    int   chosen;
};
union ShU {
    float gemm[2*16*68];
    AttnSh attn;
};

__device__ void dev_gemm(const float* __restrict__ A, const float* __restrict__ W,
                         int K, float* __restrict__ C, int M, int N,
                         const float* __restrict__ bias, float* smem) {
    float (*As)[68] = (float(*)[68])smem;
    float (*Bs)[68] = (float(*)[68])(smem + 16*68);
    const int tid = threadIdx.x;
    const int tx = tid & 15, ty = tid >> 4;
    const int lm = tid >> 2, lk = (tid & 3) << 2;
    const int tilesN = N >> 6;
    const int tiles = (M >> 6) * tilesN;
    for (int tI = blockIdx.x; tI < tiles; tI += gridDim.x) {
        const int row0 = (tI / tilesN) << 6;
        const int col0 = (tI % tilesN) << 6;
        float acc[4][4] = {};
        const float* Arow = A + (size_t)(row0 + lm) * K + lk;
        const float* Wrow = W + (size_t)(col0 + lm) * K + lk;
        for (int k0 = 0; k0 < K; k0 += 16) {
            float4 a4 = *(const float4*)(Arow + k0);
            float4 b4 = *(const float4*)(Wrow + k0);
            As[lk+0][lm]=a4.x; As[lk+1][lm]=a4.y; As[lk+2][lm]=a4.z; As[lk+3][lm]=a4.w;
            Bs[lk+0][lm]=b4.x; Bs[lk+1][lm]=b4.y; Bs[lk+2][lm]=b4.z; Bs[lk+3][lm]=b4.w;
            __syncthreads();
#pragma unroll
            for (int kk = 0; kk < 16; kk++) {
                float4 av = *(const float4*)&As[kk][ty << 2];
                float4 bv = *(const float4*)&Bs[kk][tx << 2];
                float am[4] = {av.x, av.y, av.z, av.w};
                float bn[4] = {bv.x, bv.y, bv.z, bv.w};
#pragma unroll
                for (int i = 0; i < 4; i++)
#pragma unroll
                    for (int j = 0; j < 4; j++)
                        acc[i][j] = fmaf(am[i], bn[j], acc[i][j]);
            }
            __syncthreads();
        }
#pragma unroll
        for (int i = 0; i < 4; i++) {
            int m = row0 + (ty << 2) + i;
#pragma unroll
            for (int j = 0; j < 4; j++) {
                int n = col0 + (tx << 2) + j;
                float v = acc[i][j];
                if (bias) v = __fadd_rn(v, bias[n]);
                C[(size_t)m * N + n] = v;
            }
        }
    }
}

__device__ void dev_cell(const float* __restrict__ gx, const float* __restrict__ gh,
                         const float* __restrict__ bhh,
                         float* __restrict__ h, float* __restrict__ c,
                         float* __restrict__ outh) {
    for (int idx = blockIdx.x * blockDim.x + threadIdx.x; idx < B_*H_;
         idx += gridDim.x * blockDim.x) {
        int b = idx >> 8, j = idx & (H_-1);
        const float* a = gx + (size_t)b * G4_;
        const float* d = gh + (size_t)b * G4_;
        float gi = __fadd_rn(__fadd_rn(a[j],      d[j]),      bhh[j]);
        float gf = __fadd_rn(__fadd_rn(a[j+H_],   d[j+H_]),   bhh[j+H_]);
        float gg = __fadd_rn(__fadd_rn(a[j+2*H_], d[j+2*H_]), bhh[j+2*H_]);
        float go = __fadd_rn(__fadd_rn(a[j+3*H_], d[j+3*H_]), bhh[j+3*H_]);
        float iv = xla_sigmoid(gi);
        float fv = xla_sigmoid(gf);
        float gv = xla_tanh(gg);
        float ov = xla_sigmoid(go);
        float cn = __fadd_rn(__fmul_rn(fv, c[idx]), __fmul_rn(iv, gv));
        float hn = __fmul_rn(ov, xla_tanh(cn));
        c[idx] = cn; h[idx] = hn;
        if (outh) outh[idx] = hn;
    }
}

template<int MODE>
__device__ void dev_attn(const float* __restrict__ q, const float* __restrict__ k,
                         const float* __restrict__ V, unsigned char* __restrict__ mask,
                         float* __restrict__ outq,
                         const unsigned* __restrict__ keys, const float* __restrict__ emb,
                         float* __restrict__ decin, float* __restrict__ out, int t,
                         float* skbuf, AttnSh* A) {
    const int tid = threadIdx.x;
    const int warp = tid >> 5, lane = tid & 31;
    for (int b = blockIdx.x; b < B_; b += gridDim.x) {
        float4* skv = (float4*)skbuf;
        for (int i = tid; i < S_*H_/4; i += 256) {
            int s = i >> 6, j = i & 63;
            skv[i] = ((const float4*)(k + ((size_t)s*B_ + b)*H_))[j];
        }
        A->sq[tid] = q[(size_t)b*H_ + tid];
        A->sv[tid] = V[tid];
        __syncthreads();

        for (int s = warp; s < S_; s += 8) {
            const float* krow = skbuf + s*H_;
            float p = 0.f;
#pragma unroll
            for (int r = 0; r < 8; r++) {
                int hh = lane + (r << 5);
                p = fmaf(xla_tanh(__fadd_rn(A->sq[hh], krow[hh])), A->sv[hh], p);
            }
#pragma unroll
            for (int off = 16; off > 0; off >>= 1) p += __shfl_xor_sync(0xffffffffu, p, off);
            if (lane == 0) {
                float lg = __fmul_rn(10.0f, xla_tanh(p));
                A->su[s] = mask[(size_t)b*S_ + s] ? -INFINITY : lg;
            }
        }
        __syncthreads();

        if (MODE == 0) {
            if (warp == 0) {
                float m = -INFINITY;
#pragma unroll
                for (int r = 0; r < 4; r++) { int s = lane + (r<<5); if (s < S_) m = fmaxf(m, A->su[s]); }
#pragma unroll
                for (int off = 16; off > 0; off >>= 1) m = fmaxf(m, __shfl_xor_sync(0xffffffffu, m, off));
                float sum = 0.f;
#pragma unroll
                for (int r = 0; r < 4; r++) { int s = lane + (r<<5); if (s < S_) sum += expf(__fadd_rn(A->su[s], -m)); }
#pragma unroll
                for (int off = 16; off > 0; off >>= 1) sum += __shfl_xor_sync(0xffffffffu, sum, off);
                if (lane == 0) { A->red[0] = m; A->red[1] = sum; }
            }
            __syncthreads();
            if (tid < S_) A->ws[tid] = __fdiv_rn(expf(__fadd_rn(A->su[tid], -A->red[0])), A->red[1]);
            __syncthreads();
            float acc = 0.f;
            for (int s = 0; s < S_; s++) acc = fmaf(A->ws[s], skbuf[s*H_ + tid], acc);
            outq[(size_t)b*H_ + tid] = acc;
            __syncthreads();
        } else {
            const unsigned k0 = keys[2*t], k1 = keys[2*t+1];
            if (warp == 0) {
                float best = -INFINITY; int bi = S_; float mx = -INFINITY;
#pragma unroll
                for (int r = 0; r < 4; r++) {
                    int s = lane + (r << 5);
                    if (s < S_) {
                        float lv = A->su[s];
                        mx = fmaxf(mx, lv);
                        float z = __fadd_rn(lv, gumbel_at(k0, k1, (unsigned)(b*S_ + s)));
                        if (z > best) { best = z; bi = s; }
                    }
                }
#pragma unroll
                for (int off = 16; off > 0; off >>= 1) {
                    float oz = __shfl_xor_sync(0xffffffffu, best, off);
                    int   oi = __shfl_xor_sync(0xffffffffu, bi,   off);
                    if (oz > best || (oz == best && oi < bi)) { best = oz; bi = oi; }
                    mx = fmaxf(mx, __shfl_xor_sync(0xffffffffu, mx, off));
                }
                float se = 0.f;
#pragma unroll
                for (int r = 0; r < 4; r++) { int s = lane + (r<<5); if (s < S_) se += expf(__fadd_rn(A->su[s], -mx)); }
#pragma unroll
                for (int off = 16; off > 0; off >>= 1) se += __shfl_xor_sync(0xffffffffu, se, off);
                if (lane == 0) {
                    A->chosen = bi;
                    out[(size_t)b*S_ + t] = __fadd_rn(__fadd_rn(A->su[bi], -mx), -logf(se));
                    out[(size_t)BS_ + (size_t)b*S_ + t] = (float)bi;
                    mask[(size_t)b*S_ + bi] = 1;
                }
            }
            __syncthreads();
            int ch = A->chosen;
            decin[(size_t)b*E_ + tid] = emb[((size_t)ch*B_ + b)*E_ + tid];
            __syncthreads();
        }
    }
}

__global__ __launch_bounds__(256, 2)
void mega_kernel(const float* __restrict__ inp,
                 const float* __restrict__ embW, const float* __restrict__ embB,
                 const float* __restrict__ eWih, const float* __restrict__ eWhh,
                 const float* __restrict__ ebih, const float* __restrict__ ebhh,
                 const float* __restrict__ dWih, const float* __restrict__ dWhh,
                 const float* __restrict__ dbih, const float* __restrict__ dbhh,
                 const float* __restrict__ pWq,  const float* __restrict__ pbq,
                 const float* __restrict__ pWk,  const float* __restrict__ pbk,
                 const float* __restrict__ pV,
                 const float* __restrict__ gWq,  const float* __restrict__ gbq,
                 const float* __restrict__ gWk,  const float* __restrict__ gbk,
                 const float* __restrict__ gV,
                 const float* __restrict__ sos,
                 float* __restrict__ out) {
    extern __shared__ float skbuf[];
    __shared__ ShU sh;
    const int tid = threadIdx.x;
    const int gstride = gridDim.x * blockDim.x;
    const int gidx = blockIdx.x * blockDim.x + tid;

    for (int i = gidx; i < B_*H_; i += gstride) { g_h[i] = 0.f; g_c[i] = 0.f; }
    for (int i = gidx; i < B_*E_; i += gstride) g_decin[i] = sos[i & (E_-1)];
    for (int i = gidx; i < B_*S_; i += gstride) g_mask[i] = 0;
    // Partitionable split: child t = threefry(key=(0,42), (0, t)) -> (out0, out1)
    if (blockIdx.x == 0 && tid < S_) {
        unsigned x0 = 0u, x1 = (unsigned)tid;
        threefry(0u, 42u, x0, x1);
        g_keys[2*tid]   = x0;
        g_keys[2*tid+1] = x1;
    }
    for (int idx = gidx; idx < S_*B_*E_; idx += gstride) {
        int e = idx & (E_-1);
        int i = idx >> 8;
        int s = i >> 11;
        int b = i & (B_-1);
        float x0 = inp[((size_t)b*S_ + s)*POS_ + 0];
        float x1 = inp[((size_t)b*S_ + s)*POS_ + 1];
        float dotv = fmaf(x1, embW[e*POS_ + 1], __fmul_rn(x0, embW[e*POS_ + 0]));
        g_emb[idx] = __fadd_rn(dotv, embB[e]);
    }
    gsync();

    dev_gemm(g_emb, eWih, E_, g_encgx, BS_, G4_, ebih, sh.gemm);
    gsync();

    for (int t = 0; t < S_; t++) {
        dev_gemm(g_h, eWhh, H_, g_gh, B_, G4_, nullptr, sh.gemm);
        gsync();
        dev_cell(g_encgx + (size_t)t*B_*G4_, g_gh, ebhh, g_h, g_c,
                 g_encout + (size_t)t*B_*H_);
        gsync();
    }

    dev_gemm(g_encout, pWk, H_, g_kptr, BS_, H_, pbk, sh.gemm);
    dev_gemm(g_encout, gWk, H_, g_kgl,  BS_, H_, gbk, sh.gemm);
    gsync();

    for (int t = 0; t < S_; t++) {
        dev_gemm(g_decin, dWih, E_, g_gx, B_, G4_, dbih, sh.gemm);
        dev_gemm(g_h,     dWhh, H_, g_gh, B_, G4_, nullptr, sh.gemm);
        gsync();
        dev_cell(g_gx, g_gh, dbhh, g_h, g_c, nullptr);
        gsync();
        dev_gemm(g_h, gWq, H_, g_q, B_, H_, gbq, sh.gemm);
        gsync();
        dev_attn<0>(g_q, g_kgl, gV, g_mask, g_query,
                    nullptr, nullptr, nullptr, nullptr, t, skbuf, &sh.attn);
        gsync();
        dev_gemm(g_query, pWq, H_, g_q, B_, H_, pbq, sh.gemm);
        gsync();
        dev_attn<1>(g_q, g_kptr, pV, g_mask, nullptr,
                    g_keys, g_emb, g_decin, out, t, skbuf, &sh.attn);
        gsync();
    }
}

extern "C" void kernel_launch(void* const* d_in, const int* in_sizes, int n_in,
                              void* d_out, int out_size) {
    const float* inp  = (const float*)d_in[0];
    const float* embW = (const float*)d_in[1];
    const float* embB = (const float*)d_in[2];
    const float* eWih = (const float*)d_in[3];
    const float* eWhh = (const float*)d_in[4];
    const float* ebih = (const float*)d_in[5];
    const float* ebhh = (const float*)d_in[6];
    const float* dWih = (const float*)d_in[7];
    const float* dWhh = (const float*)d_in[8];
    const float* dbih = (const float*)d_in[9];
    const float* dbhh = (const float*)d_in[10];
    const float* pWq  = (const float*)d_in[11];
    const float* pbq  = (const float*)d_in[12];
    const float* pWk  = (const float*)d_in[13];
    const float* pbk  = (const float*)d_in[14];
    const float* pV   = (const float*)d_in[15];
    const float* gWq  = (const float*)d_in[16];
    const float* gbq  = (const float*)d_in[17];
    const float* gWk  = (const float*)d_in[18];
    const float* gbk  = (const float*)d_in[19];
    const float* gV   = (const float*)d_in[20];
    const float* sos  = (const float*)d_in[21];
    float* out = (float*)d_out;

    const size_t dyn_smem = (size_t)S_ * H_ * sizeof(float);
    cudaFuncSetAttribute(mega_kernel, cudaFuncAttributeMaxDynamicSharedMemorySize, (int)dyn_smem);

    int sms = 0;
    cudaDeviceGetAttribute(&sms, cudaDevAttrMultiProcessorCount, 0);
    int nblk = sms * 2;

    mega_kernel<<<nblk, 256, dyn_smem>>>(
        inp, embW, embB, eWih, eWhh, ebih, ebhh,
        dWih, dWhh, dbih, dbhh,
        pWq, pbq, pWk, pbk, pV,
        gWq, gbq, gWk, gbk, gV, sos, out);
}

// round 10
// speedup vs baseline: 1.0633x; 1.0633x over previous
#include <cuda_runtime.h>
#include <math.h>
#include <stdint.h>

#define B_    2048
#define S_    100
#define POS_  2
#define E_    256
#define H_    256
#define G4_   1024
#define BS_   (B_*S_)

__device__ float g_emb[(size_t)S_*B_*E_];
__device__ float g_encgx[(size_t)S_*B_*G4_];
__device__ float g_encout[(size_t)S_*B_*H_];
__device__ float g_kptr[(size_t)S_*B_*H_];
__device__ float g_kgl[(size_t)S_*B_*H_];
__device__ float g_h[B_*H_];
__device__ float g_c[B_*H_];
__device__ float g_gx[B_*G4_];
__device__ float g_gh[B_*G4_];
__device__ float g_q[B_*H_];
__device__ float g_query[B_*H_];
__device__ unsigned char g_mask[B_*S_];
__device__ float g_decin[B_*E_];
__device__ unsigned g_keys[2*S_];
__device__ unsigned g_cnt = 0;
__device__ unsigned g_gen = 0;

__device__ __forceinline__ void gsync() {
    __syncthreads();
    if (threadIdx.x == 0) {
        __threadfence();
        unsigned gen = *(volatile unsigned*)&g_gen;
        if (atomicAdd(&g_cnt, 1u) == gridDim.x - 1) {
            g_cnt = 0;
            __threadfence();
            *(volatile unsigned*)&g_gen = gen + 1u;
        } else {
            while (*(volatile unsigned*)&g_gen == gen) { __nanosleep(64); }
            __threadfence();
        }
    }
    __syncthreads();
}

// ---------------- packed f32x2 (bit-exact per 32-bit half) ----------------
__device__ __forceinline__ unsigned long long pk2(float lo, float hi) {
    unsigned long long r; asm("mov.b64 %0,{%1,%2};" : "=l"(r) : "f"(lo), "f"(hi)); return r;
}
__device__ __forceinline__ void upk2(unsigned long long v, float &lo, float &hi) {
    asm("mov.b64 {%0,%1},%2;" : "=f"(lo), "=f"(hi) : "l"(v));
}
__device__ __forceinline__ unsigned long long mul2(unsigned long long a, unsigned long long b) {
    unsigned long long d; asm("mul.rn.f32x2 %0,%1,%2;" : "=l"(d) : "l"(a), "l"(b)); return d;
}
__device__ __forceinline__ unsigned long long add2(unsigned long long a, unsigned long long b) {
    unsigned long long d; asm("add.rn.f32x2 %0,%1,%2;" : "=l"(d) : "l"(a), "l"(b)); return d;
}
__device__ __forceinline__ unsigned long long fma2_(unsigned long long a, unsigned long long b,
                                                    unsigned long long c) {
    unsigned long long d; asm("fma.rn.f32x2 %0,%1,%2,%3;" : "=l"(d) : "l"(a), "l"(b), "l"(c)); return d;
}

// scalar XLA tanh (cell path)
__device__ __forceinline__ float xla_tanh(float x) {
    const float CL = 7.90531110763549805f;
    float xc = fminf(fmaxf(x, -CL), CL);
    float x2 = __fmul_rn(xc, xc);
    float p = -2.76076847742355e-16f;
    p = __fadd_rn(__fmul_rn(x2, p),  2.00018790482477e-13f);
    p = __fadd_rn(__fmul_rn(x2, p), -8.60467152213735e-11f);
    p = __fadd_rn(__fmul_rn(x2, p),  5.12229709037114e-08f);
    p = __fadd_rn(__fmul_rn(x2, p),  1.48572235717979e-05f);
    p = __fadd_rn(__fmul_rn(x2, p),  6.37261928875436e-04f);
    p = __fadd_rn(__fmul_rn(x2, p),  4.89352455891786e-03f);
    float num = __fmul_rn(xc, p);
    float q = 1.19825839466702e-06f;
    q = __fadd_rn(__fmul_rn(x2, q),  1.18534705686654e-04f);
    q = __fadd_rn(__fmul_rn(x2, q),  2.26843463243900e-03f);
    q = __fadd_rn(__fmul_rn(x2, q),  4.89352518554385e-03f);
    float r = __fdiv_rn(num, q);
    return fabsf(x) < 0.0004f ? x : r;
}
__device__ __forceinline__ float xla_sigmoid(float x) {
    return __fdiv_rn(1.0f, __fadd_rn(1.0f, expf(-x)));
}

// packed-constant set for tanh2
struct T2C { unsigned long long c[11]; };
__device__ __forceinline__ T2C make_t2c() {
    T2C t;
    t.c[0]  = pk2(-2.76076847742355e-16f, -2.76076847742355e-16f);
    t.c[1]  = pk2( 2.00018790482477e-13f,  2.00018790482477e-13f);
    t.c[2]  = pk2(-8.60467152213735e-11f, -8.60467152213735e-11f);
    t.c[3]  = pk2( 5.12229709037114e-08f,  5.12229709037114e-08f);
    t.c[4]  = pk2( 1.48572235717979e-05f,  1.48572235717979e-05f);
    t.c[5]  = pk2( 6.37261928875436e-04f,  6.37261928875436e-04f);
    t.c[6]  = pk2( 4.89352455891786e-03f,  4.89352455891786e-03f);
    t.c[7]  = pk2( 1.19825839466702e-06f,  1.19825839466702e-06f);
    t.c[8]  = pk2( 1.18534705686654e-04f,  1.18534705686654e-04f);
    t.c[9]  = pk2( 2.26843463243900e-03f,  2.26843463243900e-03f);
    t.c[10] = pk2( 4.89352518554385e-03f,  4.89352518554385e-03f);
    return t;
}
// two XLA tanh evaluations, bit-exact vs xla_tanh per element
__device__ __forceinline__ void tanh2(const T2C &K, float a, float b, float &ra, float &rb) {
    const float CL = 7.90531110763549805f;
    float ca = fminf(fmaxf(a, -CL), CL);
    float cb = fminf(fmaxf(b, -CL), CL);
    unsigned long long X  = pk2(ca, cb);
    unsigned long long X2 = mul2(X, X);
    unsigned long long P  = K.c[0];
    P = add2(mul2(X2, P), K.c[1]);
    P = add2(mul2(X2, P), K.c[2]);
    P = add2(mul2(X2, P), K.c[3]);
    P = add2(mul2(X2, P), K.c[4]);
    P = add2(mul2(X2, P), K.c[5]);
    P = add2(mul2(X2, P), K.c[6]);
    unsigned long long NUM = mul2(X, P);
    unsigned long long Q = K.c[7];
    Q = add2(mul2(X2, Q), K.c[8]);
    Q = add2(mul2(X2, Q), K.c[9]);
    Q = add2(mul2(X2, Q), K.c[10]);
    float na, nb, qa, qb;
    upk2(NUM, na, nb);
    upk2(Q, qa, qb);
    float da = __fdiv_rn(na, qa);
    float db = __fdiv_rn(nb, qb);
    ra = fabsf(a) < 0.0004f ? a : da;
    rb = fabsf(b) < 0.0004f ? b : db;
}

__device__ __forceinline__ unsigned rotl32(unsigned x, int d) {
    return (x << d) | (x >> (32 - d));
}
__device__ __forceinline__ void threefry(unsigned ks0, unsigned ks1,
                                         unsigned &x0, unsigned &x1) {
    unsigned ks2 = ks0 ^ ks1 ^ 0x1BD11BDAu;
    x0 += ks0; x1 += ks1;
#define TF_R(r) { x0 += x1; x1 = rotl32(x1, r); x1 ^= x0; }
    TF_R(13) TF_R(15) TF_R(26) TF_R(6)  x0 += ks1; x1 += ks2 + 1u;
    TF_R(17) TF_R(29) TF_R(16) TF_R(24) x0 += ks2; x1 += ks0 + 2u;
    TF_R(13) TF_R(15) TF_R(26) TF_R(6)  x0 += ks0; x1 += ks1 + 3u;
    TF_R(17) TF_R(29) TF_R(16) TF_R(24) x0 += ks1; x1 += ks2 + 4u;
    TF_R(13) TF_R(15) TF_R(26) TF_R(6)  x0 += ks2; x1 += ks0 + 5u;
#undef TF_R
}
// partitionable random_bits: bits[i] = out0 ^ out1 of threefry(key, (0, i))
__device__ __forceinline__ float gumbel_at(unsigned k0, unsigned k1, unsigned i) {
    unsigned x0 = 0u, x1 = i;
    threefry(k0, k1, x0, x1);
    unsigned bits = x0 ^ x1;
    float f = __fadd_rn(__uint_as_float((bits >> 9) | 0x3f800000u), -1.0f);
    const float TINY = 1.17549435e-38f;
    float u = fmaxf(TINY, __fadd_rn(__fmul_rn(f, 1.0f - TINY), TINY));
    return -logf(-logf(u));
}

struct AttnSh {
    float su[112];
    float ws[112];
    float red[4];
    int   chosen;
};
union ShU {
    float gemm[2*16*68];
    AttnSh attn;
};

// fp32 SGEMM, element chains identical to R9 (k-ascending fmaf, bias __fadd_rn at end);
// inner product packed over column pairs with fma.rn.f32x2 (bit-exact per element).
__device__ void dev_gemm(const float* __restrict__ A, const float* __restrict__ W,
                         int K, float* __restrict__ C, int M, int N,
                         const float* __restrict__ bias, float* smem) {
    float (*As)[68] = (float(*)[68])smem;
    float (*Bs)[68] = (float(*)[68])(smem + 16*68);
    const int tid = threadIdx.x;
    const int tx = tid & 15, ty = tid >> 4;
    const int lm = tid >> 2, lk = (tid & 3) << 2;
    const int tilesN = N >> 6;
    const int tiles = (M >> 6) * tilesN;
    for (int tI = blockIdx.x; tI < tiles; tI += gridDim.x) {
        const int row0 = (tI / tilesN) << 6;
        const int col0 = (tI % tilesN) << 6;
        unsigned long long acc[4][2];
#pragma unroll
        for (int i = 0; i < 4; i++) { acc[i][0] = 0ull; acc[i][1] = 0ull; }
        const float* Arow = A + (size_t)(row0 + lm) * K + lk;
        const float* Wrow = W + (size_t)(col0 + lm) * K + lk;
        for (int k0 = 0; k0 < K; k0 += 16) {
            float4 a4 = *(const float4*)(Arow + k0);
            float4 b4 = *(const float4*)(Wrow + k0);
            As[lk+0][lm]=a4.x; As[lk+1][lm]=a4.y; As[lk+2][lm]=a4.z; As[lk+3][lm]=a4.w;
            Bs[lk+0][lm]=b4.x; Bs[lk+1][lm]=b4.y; Bs[lk+2][lm]=b4.z; Bs[lk+3][lm]=b4.w;
            __syncthreads();
#pragma unroll
            for (int kk = 0; kk < 16; kk++) {
                float4 av = *(const float4*)&As[kk][ty << 2];
                ulonglong2 bq = *(const ulonglong2*)&Bs[kk][tx << 2];
                float am[4] = {av.x, av.y, av.z, av.w};
#pragma unroll
                for (int i = 0; i < 4; i++) {
                    unsigned long long amp = pk2(am[i], am[i]);
                    acc[i][0] = fma2_(amp, bq.x, acc[i][0]);
                    acc[i][1] = fma2_(amp, bq.y, acc[i][1]);
                }
            }
            __syncthreads();
        }
#pragma unroll
        for (int i = 0; i < 4; i++) {
            int m = row0 + (ty << 2) + i;
            float c0, c1, c2, c3;
            upk2(acc[i][0], c0, c1);
            upk2(acc[i][1], c2, c3);
            float vv[4] = {c0, c1, c2, c3};
#pragma unroll
            for (int j = 0; j < 4; j++) {
                int n = col0 + (tx << 2) + j;
                float v = vv[j];
                if (bias) v = __fadd_rn(v, bias[n]);
                C[(size_t)m * N + n] = v;
            }
        }
    }
}

__device__ void dev_cell(const float* __restrict__ gx, const float* __restrict__ gh,
                         const float* __restrict__ bhh,
                         float* __restrict__ h, float* __restrict__ c,
                         float* __restrict__ outh) {
    for (int idx = blockIdx.x * blockDim.x + threadIdx.x; idx < B_*H_;
         idx += gridDim.x * blockDim.x) {
        int b = idx >> 8, j = idx & (H_-1);
        const float* a = gx + (size_t)b * G4_;
        const float* d = gh + (size_t)b * G4_;
        float gi = __fadd_rn(__fadd_rn(a[j],      d[j]),      bhh[j]);
        float gf = __fadd_rn(__fadd_rn(a[j+H_],   d[j+H_]),   bhh[j+H_]);
        float gg = __fadd_rn(__fadd_rn(a[j+2*H_], d[j+2*H_]), bhh[j+2*H_]);
        float go = __fadd_rn(__fadd_rn(a[j+3*H_], d[j+3*H_]), bhh[j+3*H_]);
        float iv = xla_sigmoid(gi);
        float fv = xla_sigmoid(gf);
        float gv = xla_tanh(gg);
        float ov = xla_sigmoid(go);
        float cn = __fadd_rn(__fmul_rn(fv, c[idx]), __fmul_rn(iv, gv));
        float hn = __fmul_rn(ov, xla_tanh(cn));
        c[idx] = cn; h[idx] = hn;
        if (outh) outh[idx] = hn;
    }
}

// MODE 0: glimpse (smem-staged k, weighted sum). MODE 1: pointer + fused sampling
// (k read directly from global; used once).
template<int MODE>
__device__ void dev_attn(const float* __restrict__ q, const float* __restrict__ k,
                         const float* __restrict__ V, unsigned char* __restrict__ mask,
                         float* __restrict__ outq,
                         const unsigned* __restrict__ keys, const float* __restrict__ emb,
                         float* __restrict__ decin, float* __restrict__ out, int t,
                         float* skbuf, AttnSh* A) {
    const int tid = threadIdx.x;
    const int warp = tid >> 5, lane = tid & 31;
    const T2C K2 = make_t2c();
    float vv[8];
#pragma unroll
    for (int r = 0; r < 8; r++) vv[r] = V[lane + (r << 5)];

    for (int b = blockIdx.x; b < B_; b += gridDim.x) {
        if (MODE == 0) {
            float4* skv = (float4*)skbuf;
            for (int i = tid; i < S_*H_/4; i += 256) {
                int s = i >> 6, j = i & 63;
                skv[i] = ((const float4*)(k + ((size_t)s*B_ + b)*H_))[j];
            }
        }
        float qv[8];
#pragma unroll
        for (int r = 0; r < 8; r++) qv[r] = q[(size_t)b*H_ + lane + (r << 5)];
        if (MODE == 0) __syncthreads();

        for (int s = warp; s < S_; s += 8) {
            const float* krow = (MODE == 0) ? (skbuf + s*H_)
                                            : (k + ((size_t)s*B_ + b)*H_);
            float x[8], tz[8];
#pragma unroll
            for (int r = 0; r < 8; r++) x[r] = __fadd_rn(qv[r], krow[lane + (r << 5)]);
            tanh2(K2, x[0], x[1], tz[0], tz[1]);
            tanh2(K2, x[2], x[3], tz[2], tz[3]);
            tanh2(K2, x[4], x[5], tz[4], tz[5]);
            tanh2(K2, x[6], x[7], tz[6], tz[7]);
            float p = 0.f;
#pragma unroll
            for (int r = 0; r < 8; r++) p = fmaf(tz[r], vv[r], p);
#pragma unroll
            for (int off = 16; off > 0; off >>= 1) p += __shfl_xor_sync(0xffffffffu, p, off);
            if (lane == 0) {
                float lg = __fmul_rn(10.0f, xla_tanh(p));
                A->su[s] = mask[(size_t)b*S_ + s] ? -INFINITY : lg;
            }
        }
        __syncthreads();

        if (MODE == 0) {
            if (warp == 0) {
                float m = -INFINITY;
#pragma unroll
                for (int r = 0; r < 4; r++) { int s = lane + (r<<5); if (s < S_) m = fmaxf(m, A->su[s]); }
#pragma unroll
                for (int off = 16; off > 0; off >>= 1) m = fmaxf(m, __shfl_xor_sync(0xffffffffu, m, off));
                float sum = 0.f;
#pragma unroll
                for (int r = 0; r < 4; r++) { int s = lane + (r<<5); if (s < S_) sum += expf(__fadd_rn(A->su[s], -m)); }
#pragma unroll
                for (int off = 16; off > 0; off >>= 1) sum += __shfl_xor_sync(0xffffffffu, sum, off);
                if (lane == 0) { A->red[0] = m; A->red[1] = sum; }
            }
            __syncthreads();
            if (tid < S_) A->ws[tid] = __fdiv_rn(expf(__fadd_rn(A->su[tid], -A->red[0])), A->red[1]);
            __syncthreads();
            float acc = 0.f;
            for (int s = 0; s < S_; s++) acc = fmaf(A->ws[s], skbuf[s*H_ + tid], acc);
            outq[(size_t)b*H_ + tid] = acc;
            __syncthreads();
        } else {
            const unsigned k0 = keys[2*t], k1 = keys[2*t+1];
            if (warp == 0) {
                float best = -INFINITY; int bi = S_; float mx = -INFINITY;
#pragma unroll
                for (int r = 0; r < 4; r++) {
                    int s = lane + (r << 5);
                    if (s < S_) {
                        float lv = A->su[s];
                        mx = fmaxf(mx, lv);
                        float z = __fadd_rn(lv, gumbel_at(k0, k1, (unsigned)(b*S_ + s)));
                        if (z > best) { best = z; bi = s; }
                    }
                }
#pragma unroll
                for (int off = 16; off > 0; off >>= 1) {
                    float oz = __shfl_xor_sync(0xffffffffu, best, off);
                    int   oi = __shfl_xor_sync(0xffffffffu, bi,   off);
                    if (oz > best || (oz == best && oi < bi)) { best = oz; bi = oi; }
                    mx = fmaxf(mx, __shfl_xor_sync(0xffffffffu, mx, off));
                }
                float se = 0.f;
#pragma unroll
                for (int r = 0; r < 4; r++) { int s = lane + (r<<5); if (s < S_) se += expf(__fadd_rn(A->su[s], -mx)); }
#pragma unroll
                for (int off = 16; off > 0; off >>= 1) se += __shfl_xor_sync(0xffffffffu, se, off);
                if (lane == 0) {
                    A->chosen = bi;
                    out[(size_t)b*S_ + t] = __fadd_rn(__fadd_rn(A->su[bi], -mx), -logf(se));
                    out[(size_t)BS_ + (size_t)b*S_ + t] = (float)bi;
                    mask[(size_t)b*S_ + bi] = 1;
                }
            }
            __syncthreads();
            int ch = A->chosen;
            decin[(size_t)b*E_ + tid] = emb[((size_t)ch*B_ + b)*E_ + tid];
            __syncthreads();
        }
    }
}

__global__ __launch_bounds__(256, 2)
void mega_kernel(const float* __restrict__ inp,
                 const float* __restrict__ embW, const float* __restrict__ embB,
                 const float* __restrict__ eWih, const float* __restrict__ eWhh,
                 const float* __restrict__ ebih, const float* __restrict__ ebhh,
                 const float* __restrict__ dWih, const float* __restrict__ dWhh,
                 const float* __restrict__ dbih, const float* __restrict__ dbhh,
                 const float* __restrict__ pWq,  const float* __restrict__ pbq,
                 const float* __restrict__ pWk,  const float* __restrict__ pbk,
                 const float* __restrict__ pV,
                 const float* __restrict__ gWq,  const float* __restrict__ gbq,
                 const float* __restrict__ gWk,  const float* __restrict__ gbk,
                 const float* __restrict__ gV,
                 const float* __restrict__ sos,
                 float* __restrict__ out) {
    extern __shared__ float skbuf[];
    __shared__ ShU sh;
    const int tid = threadIdx.x;
    const int gstride = gridDim.x * blockDim.x;
    const int gidx = blockIdx.x * blockDim.x + tid;

    for (int i = gidx; i < B_*H_; i += gstride) { g_h[i] = 0.f; g_c[i] = 0.f; }
    for (int i = gidx; i < B_*E_; i += gstride) g_decin[i] = sos[i & (E_-1)];
    for (int i = gidx; i < B_*S_; i += gstride) g_mask[i] = 0;
    if (blockIdx.x == 0 && tid < S_) {
        unsigned x0 = 0u, x1 = (unsigned)tid;
        threefry(0u, 42u, x0, x1);
        g_keys[2*tid]   = x0;
        g_keys[2*tid+1] = x1;
    }
    for (int idx = gidx; idx < S_*B_*E_; idx += gstride) {
        int e = idx & (E_-1);
        int i = idx >> 8;
        int s = i >> 11;
        int b = i & (B_-1);
        float x0 = inp[((size_t)b*S_ + s)*POS_ + 0];
        float x1 = inp[((size_t)b*S_ + s)*POS_ + 1];
        float dotv = fmaf(x1, embW[e*POS_ + 1], __fmul_rn(x0, embW[e*POS_ + 0]));
        g_emb[idx] = __fadd_rn(dotv, embB[e]);
    }
    gsync();

    dev_gemm(g_emb, eWih, E_, g_encgx, BS_, G4_, ebih, sh.gemm);
    gsync();

    for (int t = 0; t < S_; t++) {
        dev_gemm(g_h, eWhh, H_, g_gh, B_, G4_, nullptr, sh.gemm);
        gsync();
        dev_cell(g_encgx + (size_t)t*B_*G4_, g_gh, ebhh, g_h, g_c,
                 g_encout + (size_t)t*B_*H_);
        gsync();
    }

    dev_gemm(g_encout, pWk, H_, g_kptr, BS_, H_, pbk, sh.gemm);
    dev_gemm(g_encout, gWk, H_, g_kgl,  BS_, H_, gbk, sh.gemm);
    gsync();

    for (int t = 0; t < S_; t++) {
        dev_gemm(g_decin, dWih, E_, g_gx, B_, G4_, dbih, sh.gemm);
        dev_gemm(g_h,     dWhh, H_, g_gh, B_, G4_, nullptr, sh.gemm);
        gsync();
        dev_cell(g_gx, g_gh, dbhh, g_h, g_c, nullptr);
        gsync();
        dev_gemm(g_h, gWq, H_, g_q, B_, H_, gbq, sh.gemm);
        gsync();
        dev_attn<0>(g_q, g_kgl, gV, g_mask, g_query,
                    nullptr, nullptr, nullptr, nullptr, t, skbuf, &sh.attn);
        gsync();
        dev_gemm(g_query, pWq, H_, g_q, B_, H_, pbq, sh.gemm);
        gsync();
        dev_attn<1>(g_q, g_kptr, pV, g_mask, nullptr,
                    g_keys, g_emb, g_decin, out, t, skbuf, &sh.attn);
        gsync();
    }
}

extern "C" void kernel_launch(void* const* d_in, const int* in_sizes, int n_in,
                              void* d_out, int out_size) {
    const float* inp  = (const float*)d_in[0];
    const float* embW = (const float*)d_in[1];
    const float* embB = (const float*)d_in[2];
    const float* eWih = (const float*)d_in[3];
    const float* eWhh = (const float*)d_in[4];
    const float* ebih = (const float*)d_in[5];
    const float* ebhh = (const float*)d_in[6];
    const float* dWih = (const float*)d_in[7];
    const float* dWhh = (const float*)d_in[8];
    const float* dbih = (const float*)d_in[9];
    const float* dbhh = (const float*)d_in[10];
    const float* pWq  = (const float*)d_in[11];
    const float* pbq  = (const float*)d_in[12];
    const float* pWk  = (const float*)d_in[13];
    const float* pbk  = (const float*)d_in[14];
    const float* pV   = (const float*)d_in[15];
    const float* gWq  = (const float*)d_in[16];
    const float* gbq  = (const float*)d_in[17];
    const float* gWk  = (const float*)d_in[18];
    const float* gbk  = (const float*)d_in[19];
    const float* gV   = (const float*)d_in[20];
    const float* sos  = (const float*)d_in[21];
    float* out = (float*)d_out;

    const size_t dyn_smem = (size_t)S_ * H_ * sizeof(float);
    cudaFuncSetAttribute(mega_kernel, cudaFuncAttributeMaxDynamicSharedMemorySize, (int)dyn_smem);

    int sms = 0;
    cudaDeviceGetAttribute(&sms, cudaDevAttrMultiProcessorCount, 0);
    int nblk = sms * 2;

    mega_kernel<<<nblk, 256, dyn_smem>>>(
        inp, embW, embB, eWih, eWhh, ebih, ebhh,
        dWih, dWhh, dbih, dbhh,
        pWq, pbq, pWk, pbk, pV,
        gWq, gbq, gWk, gbk, gV, sos, out);
}

// round 11
// speedup vs baseline: 1.1638x; 1.0945x over previous
#include <cuda_runtime.h>
#include <math.h>
#include <stdint.h>

#define B_    2048
#define S_    100
#define POS_  2
#define E_    256
#define H_    256
#define G4_   1024
#define BS_   (B_*S_)

__device__ float g_emb[(size_t)S_*B_*E_];
__device__ float g_encgx[(size_t)S_*B_*G4_];   // permuted gate layout
__device__ float g_encout[(size_t)S_*B_*H_];
__device__ float g_kptr[(size_t)S_*B_*H_];
__device__ float g_kgl[(size_t)S_*B_*H_];
__device__ float g_hbuf[2][B_*H_];
__device__ float g_c[B_*H_];
__device__ float g_q[B_*H_];
__device__ float g_query[B_*H_];
__device__ unsigned char g_mask[B_*S_];
__device__ float g_decin[B_*E_];
__device__ unsigned g_keys[2*S_];
__device__ float g_eWih_p[G4_*E_];
__device__ float g_eWhh_p[G4_*H_];
__device__ float g_dWih_p[G4_*E_];
__device__ float g_dWhh_p[G4_*H_];
__device__ float g_ebih_p[G4_], g_ebhh_p[G4_], g_dbih_p[G4_], g_dbhh_p[G4_];
__device__ unsigned g_cnt = 0;
__device__ unsigned g_gen = 0;

__device__ __forceinline__ void gsync() {
    __syncthreads();
    if (threadIdx.x == 0) {
        __threadfence();
        unsigned gen = *(volatile unsigned*)&g_gen;
        if (atomicAdd(&g_cnt, 1u) == gridDim.x - 1) {
            g_cnt = 0;
            __threadfence();
            *(volatile unsigned*)&g_gen = gen + 1u;
        } else {
            while (*(volatile unsigned*)&g_gen == gen) { __nanosleep(64); }
            __threadfence();
        }
    }
    __syncthreads();
}

// ---------------- packed f32x2 ----------------
__device__ __forceinline__ unsigned long long pk2(float lo, float hi) {
    unsigned long long r; asm("mov.b64 %0,{%1,%2};" : "=l"(r) : "f"(lo), "f"(hi)); return r;
}
__device__ __forceinline__ void upk2(unsigned long long v, float &lo, float &hi) {
    asm("mov.b64 {%0,%1},%2;" : "=f"(lo), "=f"(hi) : "l"(v));
}
__device__ __forceinline__ unsigned long long mul2(unsigned long long a, unsigned long long b) {
    unsigned long long d; asm("mul.rn.f32x2 %0,%1,%2;" : "=l"(d) : "l"(a), "l"(b)); return d;
}
__device__ __forceinline__ unsigned long long add2(unsigned long long a, unsigned long long b) {
    unsigned long long d; asm("add.rn.f32x2 %0,%1,%2;" : "=l"(d) : "l"(a), "l"(b)); return d;
}
__device__ __forceinline__ unsigned long long fma2_(unsigned long long a, unsigned long long b,
                                                    unsigned long long c) {
    unsigned long long d; asm("fma.rn.f32x2 %0,%1,%2,%3;" : "=l"(d) : "l"(a), "l"(b), "l"(c)); return d;
}

__device__ __forceinline__ float xla_tanh(float x) {
    const float CL = 7.90531110763549805f;
    float xc = fminf(fmaxf(x, -CL), CL);
    float x2 = __fmul_rn(xc, xc);
    float p = -2.76076847742355e-16f;
    p = __fadd_rn(__fmul_rn(x2, p),  2.00018790482477e-13f);
    p = __fadd_rn(__fmul_rn(x2, p), -8.60467152213735e-11f);
    p = __fadd_rn(__fmul_rn(x2, p),  5.12229709037114e-08f);
    p = __fadd_rn(__fmul_rn(x2, p),  1.48572235717979e-05f);
    p = __fadd_rn(__fmul_rn(x2, p),  6.37261928875436e-04f);
    p = __fadd_rn(__fmul_rn(x2, p),  4.89352455891786e-03f);
    float num = __fmul_rn(xc, p);
    float q = 1.19825839466702e-06f;
    q = __fadd_rn(__fmul_rn(x2, q),  1.18534705686654e-04f);
    q = __fadd_rn(__fmul_rn(x2, q),  2.26843463243900e-03f);
    q = __fadd_rn(__fmul_rn(x2, q),  4.89352518554385e-03f);
    float r = __fdiv_rn(num, q);
    return fabsf(x) < 0.0004f ? x : r;
}
__device__ __forceinline__ float xla_sigmoid(float x) {
    return __fdiv_rn(1.0f, __fadd_rn(1.0f, expf(-x)));
}

struct T2C { unsigned long long c[11]; };
__device__ __forceinline__ T2C make_t2c() {
    T2C t;
    t.c[0]  = pk2(-2.76076847742355e-16f, -2.76076847742355e-16f);
    t.c[1]  = pk2( 2.00018790482477e-13f,  2.00018790482477e-13f);
    t.c[2]  = pk2(-8.60467152213735e-11f, -8.60467152213735e-11f);
    t.c[3]  = pk2( 5.12229709037114e-08f,  5.12229709037114e-08f);
    t.c[4]  = pk2( 1.48572235717979e-05f,  1.48572235717979e-05f);
    t.c[5]  = pk2( 6.37261928875436e-04f,  6.37261928875436e-04f);
    t.c[6]  = pk2( 4.89352455891786e-03f,  4.89352455891786e-03f);
    t.c[7]  = pk2( 1.19825839466702e-06f,  1.19825839466702e-06f);
    t.c[8]  = pk2( 1.18534705686654e-04f,  1.18534705686654e-04f);
    t.c[9]  = pk2( 2.26843463243900e-03f,  2.26843463243900e-03f);
    t.c[10] = pk2( 4.89352518554385e-03f,  4.89352518554385e-03f);
    return t;
}
__device__ __forceinline__ void tanh2(const T2C &K, float a, float b, float &ra, float &rb) {
    const float CL = 7.90531110763549805f;
    float ca = fminf(fmaxf(a, -CL), CL);
    float cb = fminf(fmaxf(b, -CL), CL);
    unsigned long long X  = pk2(ca, cb);
    unsigned long long X2 = mul2(X, X);
    unsigned long long P  = K.c[0];
    P = add2(mul2(X2, P), K.c[1]);
    P = add2(mul2(X2, P), K.c[2]);
    P = add2(mul2(X2, P), K.c[3]);
    P = add2(mul2(X2, P), K.c[4]);
    P = add2(mul2(X2, P), K.c[5]);
    P = add2(mul2(X2, P), K.c[6]);
    unsigned long long NUM = mul2(X, P);
    unsigned long long Q = K.c[7];
    Q = add2(mul2(X2, Q), K.c[8]);
    Q = add2(mul2(X2, Q), K.c[9]);
    Q = add2(mul2(X2, Q), K.c[10]);
    float na, nb, qa, qb;
    upk2(NUM, na, nb);
    upk2(Q, qa, qb);
    float da = __fdiv_rn(na, qa);
    float db = __fdiv_rn(nb, qb);
    ra = fabsf(a) < 0.0004f ? a : da;
    rb = fabsf(b) < 0.0004f ? b : db;
}

__device__ __forceinline__ unsigned rotl32(unsigned x, int d) {
    return (x << d) | (x >> (32 - d));
}
__device__ __forceinline__ void threefry(unsigned ks0, unsigned ks1,
                                         unsigned &x0, unsigned &x1) {
    unsigned ks2 = ks0 ^ ks1 ^ 0x1BD11BDAu;
    x0 += ks0; x1 += ks1;
#define TF_R(r) { x0 += x1; x1 = rotl32(x1, r); x1 ^= x0; }
    TF_R(13) TF_R(15) TF_R(26) TF_R(6)  x0 += ks1; x1 += ks2 + 1u;
    TF_R(17) TF_R(29) TF_R(16) TF_R(24) x0 += ks2; x1 += ks0 + 2u;
    TF_R(13) TF_R(15) TF_R(26) TF_R(6)  x0 += ks0; x1 += ks1 + 3u;
    TF_R(17) TF_R(29) TF_R(16) TF_R(24) x0 += ks1; x1 += ks2 + 4u;
    TF_R(13) TF_R(15) TF_R(26) TF_R(6)  x0 += ks2; x1 += ks0 + 5u;
#undef TF_R
}
__device__ __forceinline__ float gumbel_at(unsigned k0, unsigned k1, unsigned i) {
    unsigned x0 = 0u, x1 = i;
    threefry(k0, k1, x0, x1);
    unsigned bits = x0 ^ x1;
    float f = __fadd_rn(__uint_as_float((bits >> 9) | 0x3f800000u), -1.0f);
    const float TINY = 1.17549435e-38f;
    float u = fmaxf(TINY, __fadd_rn(__fmul_rn(f, 1.0f - TINY), TINY));
    return -logf(-logf(u));
}

struct AttnSh {
    float su[112];
    float ws[112];
    float red[4];
    int   chosen;
    unsigned char smask[112];
};
union ShU {
    float gemm[2*16*68];
    AttnSh attn;
};

// ---------------- fused gemm ----------------
// EPI 0: C = A@W^T (+A2@W2^T) + bias
// EPI 1: encoder cell epilogue: gates = (gx + acc) + bhh  (gx includes bih)
// EPI 2: decoder cell epilogue: gates = (acc + bih) + bhh (acc = x-dot then h-dot chain)
template<int EPI>
__device__ void dev_gemm_f(const float* __restrict__ A, const float* __restrict__ W, int K,
                           const float* __restrict__ A2, const float* __restrict__ W2, int K2,
                           float* __restrict__ C, int M, int N,
                           const float* __restrict__ bias,
                           const float* __restrict__ gx,
                           const float* __restrict__ bih, const float* __restrict__ bhh,
                           float* __restrict__ cst, float* __restrict__ hout,
                           float* __restrict__ encout,
                           float* smem) {
    float (*As)[68] = (float(*)[68])smem;
    float (*Bs)[68] = (float(*)[68])(smem + 16*68);
    const int tid = threadIdx.x;
    const int tx = tid & 15, ty = tid >> 4;
    const int lm = tid >> 2, lk = (tid & 3) << 2;
    const int tilesN = N >> 6;
    const int tiles = (M >> 6) * tilesN;
    const int nc1 = K >> 4;
    const int nc2 = A2 ? (K2 >> 4) : 0;
    const int nc = nc1 + nc2;
    for (int tI = blockIdx.x; tI < tiles; tI += gridDim.x) {
        const int row0 = (tI / tilesN) << 6;
        const int col0 = (tI % tilesN) << 6;
        unsigned long long acc[4][2];
#pragma unroll
        for (int i = 0; i < 4; i++) { acc[i][0] = 0ull; acc[i][1] = 0ull; }
        const float* ArowA = A + (size_t)(row0 + lm) * K + lk;
        const float* WrowA = W + (size_t)(col0 + lm) * K + lk;
        const float* ArowB = A2 ? A2 + (size_t)(row0 + lm) * K2 + lk : nullptr;
        const float* WrowB = A2 ? W2 + (size_t)(col0 + lm) * K2 + lk : nullptr;
        float4 a4 = *(const float4*)ArowA;
        float4 b4 = *(const float4*)WrowA;
        for (int c = 0; c < nc; c++) {
            As[lk+0][lm]=a4.x; As[lk+1][lm]=a4.y; As[lk+2][lm]=a4.z; As[lk+3][lm]=a4.w;
            Bs[lk+0][lm]=b4.x; Bs[lk+1][lm]=b4.y; Bs[lk+2][lm]=b4.z; Bs[lk+3][lm]=b4.w;
            __syncthreads();
            if (c + 1 < nc) {   // prefetch next chunk; latency overlaps compute
                int cn = c + 1;
                if (cn < nc1) {
                    a4 = *(const float4*)(ArowA + cn*16);
                    b4 = *(const float4*)(WrowA + cn*16);
                } else {
                    int cc = cn - nc1;
                    a4 = *(const float4*)(ArowB + cc*16);
                    b4 = *(const float4*)(WrowB + cc*16);
                }
            }
#pragma unroll
            for (int kk = 0; kk < 16; kk++) {
                float4 av = *(const float4*)&As[kk][ty << 2];
                ulonglong2 bq = *(const ulonglong2*)&Bs[kk][tx << 2];
                float am[4] = {av.x, av.y, av.z, av.w};
#pragma unroll
                for (int i = 0; i < 4; i++) {
                    unsigned long long amp = pk2(am[i], am[i]);
                    acc[i][0] = fma2_(amp, bq.x, acc[i][0]);
                    acc[i][1] = fma2_(amp, bq.y, acc[i][1]);
                }
            }
            __syncthreads();
        }
        if (EPI == 0) {
#pragma unroll
            for (int i = 0; i < 4; i++) {
                int m = row0 + (ty << 2) + i;
                float c0, c1, c2, c3;
                upk2(acc[i][0], c0, c1);
                upk2(acc[i][1], c2, c3);
                float vv[4] = {c0, c1, c2, c3};
#pragma unroll
                for (int j = 0; j < 4; j++) {
                    int n = col0 + (tx << 2) + j;
                    float v = vv[j];
                    if (bias) v = __fadd_rn(v, bias[n]);
                    C[(size_t)m * N + n] = v;
                }
            }
        } else {
            const int jq = (col0 >> 2) + tx;
            float4 bh4 = *(const float4*)&bhh[col0 + (tx << 2)];
            float4 bi4;
            if (EPI == 2) bi4 = *(const float4*)&bih[col0 + (tx << 2)];
#pragma unroll
            for (int i = 0; i < 4; i++) {
                int m = row0 + (ty << 2) + i;
                float c0, c1, c2, c3;
                upk2(acc[i][0], c0, c1);
                upk2(acc[i][1], c2, c3);
                float gi, gf, gg, go;
                if (EPI == 1) {
                    float4 gx4 = *(const float4*)&gx[(size_t)m*G4_ + col0 + (tx << 2)];
                    gi = __fadd_rn(__fadd_rn(gx4.x, c0), bh4.x);
                    gf = __fadd_rn(__fadd_rn(gx4.y, c1), bh4.y);
                    gg = __fadd_rn(__fadd_rn(gx4.z, c2), bh4.z);
                    go = __fadd_rn(__fadd_rn(gx4.w, c3), bh4.w);
                } else {
                    gi = __fadd_rn(__fadd_rn(c0, bi4.x), bh4.x);
                    gf = __fadd_rn(__fadd_rn(c1, bi4.y), bh4.y);
                    gg = __fadd_rn(__fadd_rn(c2, bi4.z), bh4.z);
                    go = __fadd_rn(__fadd_rn(c3, bi4.w), bh4.w);
                }
                float iv = xla_sigmoid(gi);
                float fv = xla_sigmoid(gf);
                float gv = xla_tanh(gg);
                float ov = xla_sigmoid(go);
                size_t ci = (size_t)m * H_ + jq;
                float cn = __fadd_rn(__fmul_rn(fv, cst[ci]), __fmul_rn(iv, gv));
                float hn = __fmul_rn(ov, xla_tanh(cn));
                cst[ci] = cn;
                hout[ci] = hn;
                if (encout) encout[ci] = hn;
            }
        }
    }
}

// MODE 0: glimpse (smem-staged k, strided access). MODE 1: pointer + sampling (global k, vectorized)
template<int MODE>
__device__ void dev_attn(const float* __restrict__ q, const float* __restrict__ k,
                         const float* __restrict__ V, unsigned char* __restrict__ mask,
                         float* __restrict__ outq,
                         const unsigned* __restrict__ keys, const float* __restrict__ emb,
                         float* __restrict__ decin, float* __restrict__ out, int t,
                         float* skbuf, AttnSh* A) {
    const int tid = threadIdx.x;
    const int warp = tid >> 5, lane = tid & 31;
    const T2C K2 = make_t2c();
    float vv[8];
    float4 v0q, v1q;
    if (MODE == 0) {
#pragma unroll
        for (int r = 0; r < 8; r++) vv[r] = V[lane + (r << 5)];
    } else {
        v0q = *(const float4*)&V[lane << 3];
        v1q = *(const float4*)&V[(lane << 3) + 4];
    }

    for (int b = blockIdx.x; b < B_; b += gridDim.x) {
        if (tid < S_) A->smask[tid] = mask[(size_t)b*S_ + tid];
        if (MODE == 0) {
            float4* skv = (float4*)skbuf;
            for (int i = tid; i < S_*H_/4; i += 256) {
                int s = i >> 6, j = i & 63;
                skv[i] = ((const float4*)(k + ((size_t)s*B_ + b)*H_))[j];
            }
        }
        float qv[8];
        float4 q0q, q1q;
        if (MODE == 0) {
#pragma unroll
            for (int r = 0; r < 8; r++) qv[r] = q[(size_t)b*H_ + lane + (r << 5)];
        } else {
            q0q = *(const float4*)&q[(size_t)b*H_ + (lane << 3)];
            q1q = *(const float4*)&q[(size_t)b*H_ + (lane << 3) + 4];
        }
        __syncthreads();

        for (int s = warp; s < S_; s += 8) {
            float x[8], tz[8];
            if (MODE == 0) {
                const float* krow = skbuf + s*H_;
#pragma unroll
                for (int r = 0; r < 8; r++) x[r] = __fadd_rn(qv[r], krow[lane + (r << 5)]);
            } else {
                const float* krow = k + ((size_t)s*B_ + b)*H_ + (lane << 3);
                float4 k0v = *(const float4*)krow;
                float4 k1v = *(const float4*)(krow + 4);
                x[0] = __fadd_rn(q0q.x, k0v.x); x[1] = __fadd_rn(q0q.y, k0v.y);
                x[2] = __fadd_rn(q0q.z, k0v.z); x[3] = __fadd_rn(q0q.w, k0v.w);
                x[4] = __fadd_rn(q1q.x, k1v.x); x[5] = __fadd_rn(q1q.y, k1v.y);
                x[6] = __fadd_rn(q1q.z, k1v.z); x[7] = __fadd_rn(q1q.w, k1v.w);
            }
            tanh2(K2, x[0], x[1], tz[0], tz[1]);
            tanh2(K2, x[2], x[3], tz[2], tz[3]);
            tanh2(K2, x[4], x[5], tz[4], tz[5]);
            tanh2(K2, x[6], x[7], tz[6], tz[7]);
            float p = 0.f;
            if (MODE == 0) {
#pragma unroll
                for (int r = 0; r < 8; r++) p = fmaf(tz[r], vv[r], p);
            } else {
                p = fmaf(tz[0], v0q.x, p); p = fmaf(tz[1], v0q.y, p);
                p = fmaf(tz[2], v0q.z, p); p = fmaf(tz[3], v0q.w, p);
                p = fmaf(tz[4], v1q.x, p); p = fmaf(tz[5], v1q.y, p);
                p = fmaf(tz[6], v1q.z, p); p = fmaf(tz[7], v1q.w, p);
            }
#pragma unroll
            for (int off = 16; off > 0; off >>= 1) p += __shfl_xor_sync(0xffffffffu, p, off);
            if (lane == 0) {
                float lg = __fmul_rn(10.0f, xla_tanh(p));
                A->su[s] = A->smask[s] ? -INFINITY : lg;
            }
        }
        __syncthreads();

        if (MODE == 0) {
            if (warp == 0) {
                float m = -INFINITY;
#pragma unroll
                for (int r = 0; r < 4; r++) { int s = lane + (r<<5); if (s < S_) m = fmaxf(m, A->su[s]); }
#pragma unroll
                for (int off = 16; off > 0; off >>= 1) m = fmaxf(m, __shfl_xor_sync(0xffffffffu, m, off));
                float sum = 0.f;
#pragma unroll
                for (int r = 0; r < 4; r++) { int s = lane + (r<<5); if (s < S_) sum += expf(__fadd_rn(A->su[s], -m)); }
#pragma unroll
                for (int off = 16; off > 0; off >>= 1) sum += __shfl_xor_sync(0xffffffffu, sum, off);
                if (lane == 0) { A->red[0] = m; A->red[1] = sum; }
            }
            __syncthreads();
            if (tid < S_) A->ws[tid] = __fdiv_rn(expf(__fadd_rn(A->su[tid], -A->red[0])), A->red[1]);
            __syncthreads();
            float acc = 0.f;
            for (int s = 0; s < S_; s++) acc = fmaf(A->ws[s], skbuf[s*H_ + tid], acc);
            outq[(size_t)b*H_ + tid] = acc;
            __syncthreads();
        } else {
            const unsigned k0 = keys[2*t], k1 = keys[2*t+1];
            if (warp == 0) {
                float best = -INFINITY; int bi = S_; float mx = -INFINITY;
#pragma unroll
                for (int r = 0; r < 4; r++) {
                    int s = lane + (r << 5);
                    if (s < S_) {
                        float lv = A->su[s];
                        mx = fmaxf(mx, lv);
                        float z = __fadd_rn(lv, gumbel_at(k0, k1, (unsigned)(b*S_ + s)));
                        if (z > best) { best = z; bi = s; }
                    }
                }
#pragma unroll
                for (int off = 16; off > 0; off >>= 1) {
                    float oz = __shfl_xor_sync(0xffffffffu, best, off);
                    int   oi = __shfl_xor_sync(0xffffffffu, bi,   off);
                    if (oz > best || (oz == best && oi < bi)) { best = oz; bi = oi; }
                    mx = fmaxf(mx, __shfl_xor_sync(0xffffffffu, mx, off));
                }
                float se = 0.f;
#pragma unroll
                for (int r = 0; r < 4; r++) { int s = lane + (r<<5); if (s < S_) se += expf(__fadd_rn(A->su[s], -mx)); }
#pragma unroll
                for (int off = 16; off > 0; off >>= 1) se += __shfl_xor_sync(0xffffffffu, se, off);
                if (lane == 0) {
                    A->chosen = bi;
                    out[(size_t)b*S_ + t] = __fadd_rn(__fadd_rn(A->su[bi], -mx), -logf(se));
                    out[(size_t)BS_ + (size_t)b*S_ + t] = (float)bi;
                    mask[(size_t)b*S_ + bi] = 1;
                }
            }
            __syncthreads();
            int ch = A->chosen;
            decin[(size_t)b*E_ + tid] = emb[((size_t)ch*B_ + b)*E_ + tid];
            __syncthreads();
        }
    }
}

__global__ __launch_bounds__(256, 2)
void mega_kernel(const float* __restrict__ inp,
                 const float* __restrict__ embW, const float* __restrict__ embB,
                 const float* __restrict__ eWih, const float* __restrict__ eWhh,
                 const float* __restrict__ ebih, const float* __restrict__ ebhh,
                 const float* __restrict__ dWih, const float* __restrict__ dWhh,
                 const float* __restrict__ dbih, const float* __restrict__ dbhh,
                 const float* __restrict__ pWq,  const float* __restrict__ pbq,
                 const float* __restrict__ pWk,  const float* __restrict__ pbk,
                 const float* __restrict__ pV,
                 const float* __restrict__ gWq,  const float* __restrict__ gbq,
                 const float* __restrict__ gWk,  const float* __restrict__ gbk,
                 const float* __restrict__ gV,
                 const float* __restrict__ sos,
                 float* __restrict__ out) {
    extern __shared__ float skbuf[];
    __shared__ ShU sh;
    const int tid = threadIdx.x;
    const int gstride = gridDim.x * blockDim.x;
    const int gidx = blockIdx.x * blockDim.x + tid;

    // phase 0: init, weight permutes, keys, embedding
    for (int i = gidx; i < B_*H_; i += gstride) { g_hbuf[0][i] = 0.f; g_c[i] = 0.f; }
    for (int i = gidx; i < B_*E_; i += gstride) g_decin[i] = sos[i & (E_-1)];
    for (int i = gidx; i < B_*S_; i += gstride) g_mask[i] = 0;
    for (int idx = gidx; idx < G4_*E_; idx += gstride) {
        int row = idx >> 8, kk = idx & 255;
        int j = row >> 2, g = row & 3;
        int old = (g*H_ + j)*E_ + kk;
        g_eWih_p[idx] = eWih[old];
        g_eWhh_p[idx] = eWhh[old];
        g_dWih_p[idx] = dWih[old];
        g_dWhh_p[idx] = dWhh[old];
    }
    for (int idx = gidx; idx < G4_; idx += gstride) {
        int j = idx >> 2, g = idx & 3;
        int old = g*H_ + j;
        g_ebih_p[idx] = ebih[old];
        g_ebhh_p[idx] = ebhh[old];
        g_dbih_p[idx] = dbih[old];
        g_dbhh_p[idx] = dbhh[old];
    }
    if (blockIdx.x == 0 && tid < S_) {
        unsigned x0 = 0u, x1 = (unsigned)tid;
        threefry(0u, 42u, x0, x1);
        g_keys[2*tid]   = x0;
        g_keys[2*tid+1] = x1;
    }
    for (int idx = gidx; idx < S_*B_*E_; idx += gstride) {
        int e = idx & (E_-1);
        int i = idx >> 8;
        int s = i >> 11;
        int b = i & (B_-1);
        float x0 = inp[((size_t)b*S_ + s)*POS_ + 0];
        float x1 = inp[((size_t)b*S_ + s)*POS_ + 1];
        float dotv = fmaf(x1, embW[e*POS_ + 1], __fmul_rn(x0, embW[e*POS_ + 0]));
        g_emb[idx] = __fadd_rn(dotv, embB[e]);
    }
    gsync();

    // encoder input gates (permuted layout), all timesteps
    dev_gemm_f<0>(g_emb, g_eWih_p, E_, nullptr, nullptr, 0, g_encgx, BS_, G4_,
                  g_ebih_p, nullptr, nullptr, nullptr, nullptr, nullptr, nullptr, sh.gemm);
    gsync();

    // encoder recurrence: gemm + fused LSTM epilogue, ping-pong h
    for (int t = 0; t < S_; t++) {
        dev_gemm_f<1>(g_hbuf[t & 1], g_eWhh_p, H_, nullptr, nullptr, 0,
                      nullptr, B_, G4_, nullptr,
                      g_encgx + (size_t)t*B_*G4_, nullptr, g_ebhh_p,
                      g_c, g_hbuf[(t + 1) & 1], g_encout + (size_t)t*B_*H_, sh.gemm);
        gsync();
    }
    // final encoder h is in g_hbuf[0]

    dev_gemm_f<0>(g_encout, pWk, H_, nullptr, nullptr, 0, g_kptr, BS_, H_,
                  pbk, nullptr, nullptr, nullptr, nullptr, nullptr, nullptr, sh.gemm);
    dev_gemm_f<0>(g_encout, gWk, H_, nullptr, nullptr, 0, g_kgl, BS_, H_,
                  gbk, nullptr, nullptr, nullptr, nullptr, nullptr, nullptr, sh.gemm);
    gsync();

    // decoder
    for (int t = 0; t < S_; t++) {
        // fused gate gemm (x-pass then h-pass) + LSTM epilogue
        dev_gemm_f<2>(g_decin, g_dWih_p, E_, g_hbuf[t & 1], g_dWhh_p, H_,
                      nullptr, B_, G4_, nullptr,
                      nullptr, g_dbih_p, g_dbhh_p,
                      g_c, g_hbuf[(t + 1) & 1], nullptr, sh.gemm);
        gsync();
        float* hcur = g_hbuf[(t + 1) & 1];
        dev_gemm_f<0>(hcur, gWq, H_, nullptr, nullptr, 0, g_q, B_, H_,
                      gbq, nullptr, nullptr, nullptr, nullptr, nullptr, nullptr, sh.gemm);
        gsync();
        dev_attn<0>(g_q, g_kgl, gV, g_mask, g_query,
                    nullptr, nullptr, nullptr, nullptr, t, skbuf, &sh.attn);
        gsync();
        dev_gemm_f<0>(g_query, pWq, H_, nullptr, nullptr, 0, g_q, B_, H_,
                      pbq, nullptr, nullptr, nullptr, nullptr, nullptr, nullptr, sh.gemm);
        gsync();
        dev_attn<1>(g_q, g_kptr, pV, g_mask, nullptr,
                    g_keys, g_emb, g_decin, out, t, skbuf, &sh.attn);
        gsync();
    }
}

extern "C" void kernel_launch(void* const* d_in, const int* in_sizes, int n_in,
                              void* d_out, int out_size) {
    const float* inp  = (const float*)d_in[0];
    const float* embW = (const float*)d_in[1];
    const float* embB = (const float*)d_in[2];
    const float* eWih = (const float*)d_in[3];
    const float* eWhh = (const float*)d_in[4];
    const float* ebih = (const float*)d_in[5];
    const float* ebhh = (const float*)d_in[6];
    const float* dWih = (const float*)d_in[7];
    const float* dWhh = (const float*)d_in[8];
    const float* dbih = (const float*)d_in[9];
    const float* dbhh = (const float*)d_in[10];
    const float* pWq  = (const float*)d_in[11];
    const float* pbq  = (const float*)d_in[12];
    const float* pWk  = (const float*)d_in[13];
    const float* pbk  = (const float*)d_in[14];
    const float* pV   = (const float*)d_in[15];
    const float* gWq  = (const float*)d_in[16];
    const float* gbq  = (const float*)d_in[17];
    const float* gWk  = (const float*)d_in[18];
    const float* gbk  = (const float*)d_in[19];
    const float* gV   = (const float*)d_in[20];
    const float* sos  = (const float*)d_in[21];
    float* out = (float*)d_out;

    const size_t dyn_smem = (size_t)S_ * H_ * sizeof(float);
    cudaFuncSetAttribute(mega_kernel, cudaFuncAttributeMaxDynamicSharedMemorySize, (int)dyn_smem);

    int sms = 0;
    cudaDeviceGetAttribute(&sms, cudaDevAttrMultiProcessorCount, 0);
    int nblk = sms * 2;

    mega_kernel<<<nblk, 256, dyn_smem>>>(
        inp, embW, embB, eWih, eWhh, ebih, ebhh,
        dWih, dWhh, dbih, dbhh,
        pWq, pbq, pWk, pbk, pV,
        gWq, gbq, gWk, gbk, gV, sos, out);
}